// round 16
// baseline (speedup 1.0000x reference)
#include <cuda_runtime.h>
#include <cuda_bf16.h>
#include <cstdint>

#define NN 100000
#define NE 1600000
#define D 128
#define CAP 96

// Scratch (no allocations allowed)
__device__ float          g_neigh[(size_t)NN * D];  // neighbor MEANS (fp32)
__device__ __nv_bfloat16  g_hbf[(size_t)NN * D];    // bf16 shadow of h
__device__ int            g_cnt[NN];                // in-degree (zero at entry; agg re-zeroes)
__device__ int            g_bins[(size_t)NN * CAP]; // per-dst src lists

// ---------------------------------------------------------------------------
// stage1: merged prep + bin (R15, measured 35.6us).
// ---------------------------------------------------------------------------
#define NB_PREP ((NN * D / 4 + 255) / 256)   // 12500

__global__ void __launch_bounds__(256) stage1_kernel(
    const float* __restrict__ h,
    const int* __restrict__ src32,
    const int* __restrict__ dst32,
    int n_edges)
{
    const int tid = threadIdx.x;
    if (blockIdx.x < NB_PREP) {
        const int NH = NN * D / 4;
        int idx = blockIdx.x * 256 + tid;
        if (idx < NH) {
            float4 v = reinterpret_cast<const float4*>(h)[idx];
            uint32_t p0, p1;
            asm("cvt.rn.bf16x2.f32 %0, %1, %2;" : "=r"(p0) : "f"(v.y), "f"(v.x));
            asm("cvt.rn.bf16x2.f32 %0, %1, %2;" : "=r"(p1) : "f"(v.w), "f"(v.z));
            reinterpret_cast<uint2*>(g_hbf)[idx] = make_uint2(p0, p1);
        }
        return;
    }

    __shared__ int flag;
    if (tid == 0) flag = 0;
    __syncthreads();
    if (src32[2 * tid + 1] != 0) flag = 1;   // int64 LE high words are 0
    __syncthreads();
    const int fmt = flag;                    // 1 = int32, 0 = int64

    int e = (blockIdx.x - NB_PREP) * 256 + tid;
    if (e >= n_edges) return;
    int s, d;
    if (fmt) { s = src32[e];     d = dst32[e];     }
    else     { s = src32[2 * e]; d = dst32[2 * e]; }
    int pos = atomicAdd(&g_cnt[d], 1);
    if (pos < CAP) g_bins[(size_t)d * CAP + pos] = s;
}

// bf16x2 decode: bf16 is the top half of fp32.
__device__ __forceinline__ float blo(uint32_t u) { return __uint_as_float(u << 16); }
__device__ __forceinline__ float bhi(uint32_t u) { return __uint_as_float(u & 0xFFFF0000u); }

// Aggregate one 128-node tile with 8 producer warps (warp-per-node x16).
// R9 agg body; zeroes g_cnt[w] after reading (clean state for graph replay).
__device__ __forceinline__ void agg_tile(int tile, int n_nodes, int wida, int lane) {
    const int base = tile * 128;
    const __nv_bfloat16* hb = g_hbf;
    #pragma unroll 1
    for (int j = 0; j < 16; j++) {
        int w = base + wida + j * 8;
        if (w >= n_nodes) continue;
        int cnt = g_cnt[w];
        int deg = min(cnt, CAP);
        const int* bp = g_bins + (size_t)w * CAP;

        float a0 = 0.f, a1 = 0.f, a2 = 0.f, a3 = 0.f;
        int i = 0;
        for (; i + 4 <= deg; i += 4) {
            int s0 = bp[i], s1 = bp[i + 1], s2 = bp[i + 2], s3 = bp[i + 3];
            uint2 u0 = *reinterpret_cast<const uint2*>(hb + (size_t)s0 * D + lane * 4);
            uint2 u1 = *reinterpret_cast<const uint2*>(hb + (size_t)s1 * D + lane * 4);
            uint2 u2 = *reinterpret_cast<const uint2*>(hb + (size_t)s2 * D + lane * 4);
            uint2 u3 = *reinterpret_cast<const uint2*>(hb + (size_t)s3 * D + lane * 4);
            a0 += (blo(u0.x) + blo(u1.x)) + (blo(u2.x) + blo(u3.x));
            a1 += (bhi(u0.x) + bhi(u1.x)) + (bhi(u2.x) + bhi(u3.x));
            a2 += (blo(u0.y) + blo(u1.y)) + (blo(u2.y) + blo(u3.y));
            a3 += (bhi(u0.y) + bhi(u1.y)) + (bhi(u2.y) + bhi(u3.y));
        }
        for (; i < deg; i++) {
            int s = bp[i];
            uint2 u = *reinterpret_cast<const uint2*>(hb + (size_t)s * D + lane * 4);
            a0 += blo(u.x); a1 += bhi(u.x); a2 += blo(u.y); a3 += bhi(u.y);
        }
        float inv = 1.0f / (float)max(cnt, 1);
        float4 r = make_float4(a0 * inv, a1 * inv, a2 * inv, a3 * inv);
        *reinterpret_cast<float4*>(g_neigh + (size_t)w * D + lane * 4) = r;
        if (lane == 0) g_cnt[w] = 0;
    }
}

// ---------------------------------------------------------------------------
// Fused warp-specialized kernel: warps 0-7 GEMM tile t (tf32 mma, R9 microtile,
// BM=128), warps 8-15 aggregate tile t+1. Named barrier 1 for GEMM-internal
// syncs; one __syncthreads per iteration for the handoff.
// ---------------------------------------------------------------------------
#define BPITCH 264
#define APITCH 36
#define BM 128
#define SMEM_BYTES (128 * BPITCH * 4 + 2 * BM * APITCH * 4 + 1024)  // ~173KB

#define BARG() asm volatile("bar.sync 1, 256;" ::: "memory")

__device__ __forceinline__ uint32_t tf32r(float x) {
    uint32_t t;
    asm("cvt.rna.tf32.f32 %0, %1;" : "=r"(t) : "f"(x));
    return t;
}

__device__ __forceinline__ void mma1688(float* c, const uint32_t* a,
                                        uint32_t b0, uint32_t b1) {
    asm volatile(
        "mma.sync.aligned.m16n8k8.row.col.f32.tf32.tf32.f32 "
        "{%0,%1,%2,%3}, {%4,%5,%6,%7}, {%8,%9}, {%0,%1,%2,%3};"
        : "+f"(c[0]), "+f"(c[1]), "+f"(c[2]), "+f"(c[3])
        : "r"(a[0]), "r"(a[1]), "r"(a[2]), "r"(a[3]), "r"(b0), "r"(b1));
}

__global__ void __launch_bounds__(512, 1) fused_kernel(
    const float* __restrict__ h,
    const float* __restrict__ Wself,
    const float* __restrict__ Wneigh,
    const float* __restrict__ bias,
    float* __restrict__ out,
    int n_nodes)
{
    extern __shared__ char smem[];
    uint32_t* Bs = (uint32_t*)smem;                 // [128][BPITCH] tf32, k-permuted
    uint32_t* As = Bs + 128 * BPITCH;               // 2 bufs x [BM][APITCH]
    float* sbias = (float*)(As + 2 * BM * APITCH);

    const int tid  = threadIdx.x;
    const int wid  = tid >> 5;
    const int lane = tid & 31;

    const int ntiles = (n_nodes + 127) >> 7;        // 782
    const int iters  = (ntiles + 147) / 148;        // 6

    // ---- prologue: consumers stage Bs; producers aggregate tile_0 ----
    if (tid < 256) {
        for (int u = tid; u < 128 * 128; u += 256) {
            int j = u >> 7, k = u & 127;
            int kin = k & 7;
            int kp = (k & ~7) | (((kin & 3) << 1) | (kin >> 2));
            Bs[j * BPITCH + kp]       = tf32r(Wself[u]);
            Bs[j * BPITCH + 128 + kp] = tf32r(Wneigh[u]);
        }
        if (tid < 128) sbias[tid] = bias[tid];
    } else {
        if (blockIdx.x < ntiles)
            agg_tile(blockIdx.x, n_nodes, wid - 8, lane);
    }
    __syncthreads();

    const int wm = (wid >> 1) * 32;     // GEMM warps: 0,32,64,96
    const int wn = (wid & 1) * 64;      // 0,64

    #pragma unroll 1
    for (int it = 0; it < iters; it++) {
        const int tile = blockIdx.x + it * 148;

        if (tid < 256) {
            if (tile < ntiles) {
                const int nodeBase = tile * BM;

                float acc[2][8][4];
                #pragma unroll
                for (int mi = 0; mi < 2; mi++)
                    #pragma unroll
                    for (int ni = 0; ni < 8; ni++)
                        #pragma unroll
                        for (int q = 0; q < 4; q++) acc[mi][ni][q] = 0.f;

                // prefetch chunk 0
                float4 pv[4];
                #pragma unroll
                for (int i = 0; i < 4; i++) {
                    int u = tid + i * 256;
                    int r = u >> 3, f4 = u & 7;
                    int node = nodeBase + r;
                    pv[i] = (node < n_nodes)
                        ? *reinterpret_cast<const float4*>(h + (size_t)node * D + f4 * 4)
                        : make_float4(0.f, 0.f, 0.f, 0.f);
                }

                #pragma unroll 1
                for (int c = 0; c < 8; c++) {
                    uint32_t* bufA = As + (c & 1) * (BM * APITCH);

                    #pragma unroll
                    for (int i = 0; i < 4; i++) {
                        int u = tid + i * 256;
                        int r = u >> 3, f4 = u & 7;
                        uint32_t* p = bufA + r * APITCH + f4 * 4;
                        p[0] = tf32r(pv[i].x);
                        p[1] = tf32r(pv[i].y);
                        p[2] = tf32r(pv[i].z);
                        p[3] = tf32r(pv[i].w);
                    }

                    if (c < 7) {
                        const int cn = c + 1;
                        const float* X = (cn < 4) ? h : g_neigh;
                        const int koff = (cn & 3) * 32;
                        #pragma unroll
                        for (int i = 0; i < 4; i++) {
                            int u = tid + i * 256;
                            int r = u >> 3, f4 = u & 7;
                            int node = nodeBase + r;
                            pv[i] = (node < n_nodes)
                                ? *reinterpret_cast<const float4*>(X + (size_t)node * D + koff + f4 * 4)
                                : make_float4(0.f, 0.f, 0.f, 0.f);
                        }
                    }
                    BARG();

                    #pragma unroll
                    for (int kf = 0; kf < 4; kf++) {
                        const int kb = kf * 8;
                        uint32_t a[2][4];
                        #pragma unroll
                        for (int mi = 0; mi < 2; mi++) {
                            const uint32_t* pa =
                                bufA + (wm + mi * 16 + (lane >> 2)) * APITCH + kb + (lane & 3);
                            a[mi][0] = pa[0];
                            a[mi][1] = pa[8 * APITCH];
                            a[mi][2] = pa[4];
                            a[mi][3] = pa[8 * APITCH + 4];
                        }
                        #pragma unroll
                        for (int ni = 0; ni < 8; ni++) {
                            const uint2 bb = *reinterpret_cast<const uint2*>(
                                Bs + (wn + ni * 8 + (lane >> 2)) * BPITCH + c * 32 + kb + 2 * (lane & 3));
                            #pragma unroll
                            for (int mi = 0; mi < 2; mi++)
                                mma1688(acc[mi][ni], a[mi], bb.x, bb.y);
                        }
                    }
                    BARG();
                }

                #pragma unroll
                for (int mi = 0; mi < 2; mi++) {
                    int r0 = nodeBase + wm + mi * 16 + (lane >> 2);
                    int r1 = r0 + 8;
                    #pragma unroll
                    for (int ni = 0; ni < 8; ni++) {
                        int col = wn + ni * 8 + (lane & 3) * 2;
                        float b0 = sbias[col], b1 = sbias[col + 1];
                        if (r0 < n_nodes) {
                            float2 v = make_float2(acc[mi][ni][0] + b0, acc[mi][ni][1] + b1);
                            *reinterpret_cast<float2*>(out + (size_t)r0 * D + col) = v;
                        }
                        if (r1 < n_nodes) {
                            float2 v = make_float2(acc[mi][ni][2] + b0, acc[mi][ni][3] + b1);
                            *reinterpret_cast<float2*>(out + (size_t)r1 * D + col) = v;
                        }
                    }
                }
            }
        } else {
            // producers: aggregate tile for NEXT iteration
            int atile = blockIdx.x + (it + 1) * 148;
            if (atile < ntiles)
                agg_tile(atile, n_nodes, wid - 8, lane);
        }
        __syncthreads();   // handoff: tile_{it+1}'s neigh now visible
    }
}

// ---------------------------------------------------------------------------
extern "C" void kernel_launch(void* const* d_in, const int* in_sizes, int n_in,
                              void* d_out, int out_size)
{
    const float* h      = (const float*)d_in[0];
    const int*   src32  = (const int*)d_in[1];
    const int*   dst32  = (const int*)d_in[2];
    const float* Wself  = (const float*)d_in[3];
    const float* Wneigh = (const float*)d_in[4];
    const float* bias   = (const float*)d_in[5];
    float*       out    = (float*)d_out;

    const int n_nodes = in_sizes[0] / D;
    const int n_edges = in_sizes[1];

    static int attr_set = 0;
    if (!attr_set) {
        cudaFuncSetAttribute(fused_kernel,
                             cudaFuncAttributeMaxDynamicSharedMemorySize, SMEM_BYTES);
        attr_set = 1;
    }

    const int nb_bin = (n_edges + 255) / 256;
    stage1_kernel<<<NB_PREP + nb_bin, 256>>>(h, src32, dst32, n_edges);
    fused_kernel<<<148, 512, SMEM_BYTES>>>(h, Wself, Wneigh, bias, out, n_nodes);
}

// round 17
// speedup vs baseline: 2.1927x; 2.1927x over previous
#include <cuda_runtime.h>
#include <cuda_bf16.h>
#include <cstdint>

#define NN 100000
#define NE 1600000
#define D 128
#define CAP 96

// Scratch (no allocations allowed)
__device__ float          g_neigh[(size_t)NN * D];  // neighbor MEANS (fp32)
__device__ __nv_bfloat16  g_hbf[(size_t)NN * D];    // bf16 shadow of h
__device__ int            g_cnt[NN];                // in-degree counters
__device__ int            g_bins[(size_t)NN * CAP]; // per-dst src lists

// ---------------------------------------------------------------------------
// prep: h -> bf16 shadow AND zero g_cnt (R9 byte-identical).
// ---------------------------------------------------------------------------
__global__ void __launch_bounds__(256) prep_kernel(const float* __restrict__ h) {
    const int NH = NN * D / 4;          // float4 units
    int idx = blockIdx.x * blockDim.x + threadIdx.x;
    if (idx < NH) {
        float4 v = reinterpret_cast<const float4*>(h)[idx];
        uint32_t p0, p1;
        asm("cvt.rn.bf16x2.f32 %0, %1, %2;" : "=r"(p0) : "f"(v.y), "f"(v.x));
        asm("cvt.rn.bf16x2.f32 %0, %1, %2;" : "=r"(p1) : "f"(v.w), "f"(v.z));
        reinterpret_cast<uint2*>(g_hbf)[idx] = make_uint2(p0, p1);
    } else if (idx < NH + NN / 4) {
        reinterpret_cast<int4*>(g_cnt)[idx - NH] = make_int4(0, 0, 0, 0);
    }
}

// ---------------------------------------------------------------------------
// bin: inline per-block format vote + vectorized edge-pair loads.
//   int64 LE: odd 32-bit words of the first 256 entries are all zero;
//   int32: 256 random indices in [0,1e5) all zero is impossible.
// Each thread handles 2 edges: int4 (int64 path) / int2 (int32 path) loads,
// fully coalesced either way.
// ---------------------------------------------------------------------------
__global__ void __launch_bounds__(256) bin_kernel(
    const int* __restrict__ src32, const int* __restrict__ dst32, int n_edges)
{
    const int tid = threadIdx.x;
    __shared__ int flag;
    if (tid == 0) flag = 0;
    __syncthreads();
    if (src32[2 * tid + 1] != 0) flag = 1;
    __syncthreads();
    const int fmt = flag;               // 1 = int32, 0 = int64

    int p = blockIdx.x * 256 + tid;     // edge pair index
    int e0 = 2 * p;
    if (e0 >= n_edges) return;
    bool has2 = (e0 + 1) < n_edges;

    int s0, d0, s1 = 0, d1 = 0;
    if (fmt) {
        int2 sv = *reinterpret_cast<const int2*>(src32 + e0);
        int2 dv = *reinterpret_cast<const int2*>(dst32 + e0);
        s0 = sv.x; s1 = sv.y; d0 = dv.x; d1 = dv.y;
    } else {
        int4 sv = *reinterpret_cast<const int4*>(src32 + 2 * e0);
        int4 dv = *reinterpret_cast<const int4*>(dst32 + 2 * e0);
        s0 = sv.x; s1 = sv.z; d0 = dv.x; d1 = dv.z;
    }

    int pos0 = atomicAdd(&g_cnt[d0], 1);
    if (pos0 < CAP) g_bins[(size_t)d0 * CAP + pos0] = s0;
    if (has2) {
        int pos1 = atomicAdd(&g_cnt[d1], 1);
        if (pos1 < CAP) g_bins[(size_t)d1 * CAP + pos1] = s1;
    }
}

// bf16x2 decode: bf16 is the top half of fp32.
__device__ __forceinline__ float blo(uint32_t u) { return __uint_as_float(u << 16); }
__device__ __forceinline__ float bhi(uint32_t u) { return __uint_as_float(u & 0xFFFF0000u); }

// Warp-per-node gather-mean over bf16 rows, unroll-4 (R9 byte-identical).
__global__ void __launch_bounds__(256) agg_kernel(int n_nodes) {
    int w = (blockIdx.x * 256 + threadIdx.x) >> 5;
    if (w >= n_nodes) return;
    int lane = threadIdx.x & 31;

    int cnt = g_cnt[w];
    int deg = min(cnt, CAP);
    const int* bp = g_bins + (size_t)w * CAP;
    const __nv_bfloat16* hb = g_hbf;

    float a0 = 0.f, a1 = 0.f, a2 = 0.f, a3 = 0.f;
    int i = 0;
    for (; i + 4 <= deg; i += 4) {
        int s0 = bp[i], s1 = bp[i + 1], s2 = bp[i + 2], s3 = bp[i + 3];
        uint2 u0 = *reinterpret_cast<const uint2*>(hb + (size_t)s0 * D + lane * 4);
        uint2 u1 = *reinterpret_cast<const uint2*>(hb + (size_t)s1 * D + lane * 4);
        uint2 u2 = *reinterpret_cast<const uint2*>(hb + (size_t)s2 * D + lane * 4);
        uint2 u3 = *reinterpret_cast<const uint2*>(hb + (size_t)s3 * D + lane * 4);
        a0 += (blo(u0.x) + blo(u1.x)) + (blo(u2.x) + blo(u3.x));
        a1 += (bhi(u0.x) + bhi(u1.x)) + (bhi(u2.x) + bhi(u3.x));
        a2 += (blo(u0.y) + blo(u1.y)) + (blo(u2.y) + blo(u3.y));
        a3 += (bhi(u0.y) + bhi(u1.y)) + (bhi(u2.y) + bhi(u3.y));
    }
    for (; i < deg; i++) {
        int s = bp[i];
        uint2 u = *reinterpret_cast<const uint2*>(hb + (size_t)s * D + lane * 4);
        a0 += blo(u.x); a1 += bhi(u.x); a2 += blo(u.y); a3 += bhi(u.y);
    }
    float inv = 1.0f / (float)max(cnt, 1);
    float4 r = make_float4(a0 * inv, a1 * inv, a2 * inv, a3 * inv);
    *reinterpret_cast<float4*>(g_neigh + (size_t)w * D + lane * 4) = r;
}

// ---------------------------------------------------------------------------
// Single-pass TF32 GEMM via mma.sync.m16n8k8 (R9 byte-identical).
// ---------------------------------------------------------------------------
#define BPITCH 264
#define APITCH 36
#define BM 256
#define BBYTES (128 * BPITCH * 4)
#define ABYTES (2 * BM * APITCH * 4)
#define SMEM_BYTES (BBYTES + ABYTES + 1024)

__device__ __forceinline__ uint32_t tf32r(float x) {
    uint32_t t;
    asm("cvt.rna.tf32.f32 %0, %1;" : "=r"(t) : "f"(x));
    return t;
}

__device__ __forceinline__ void mma1688(float* c, const uint32_t* a,
                                        uint32_t b0, uint32_t b1) {
    asm volatile(
        "mma.sync.aligned.m16n8k8.row.col.f32.tf32.tf32.f32 "
        "{%0,%1,%2,%3}, {%4,%5,%6,%7}, {%8,%9}, {%0,%1,%2,%3};"
        : "+f"(c[0]), "+f"(c[1]), "+f"(c[2]), "+f"(c[3])
        : "r"(a[0]), "r"(a[1]), "r"(a[2]), "r"(a[3]), "r"(b0), "r"(b1));
}

__global__ void __launch_bounds__(512, 1) sage_mma_kernel(
    const float* __restrict__ h,
    const float* __restrict__ Wself,
    const float* __restrict__ Wneigh,
    const float* __restrict__ bias,
    float* __restrict__ out,
    int n_nodes)
{
    extern __shared__ char smem[];
    uint32_t* Bs = (uint32_t*)smem;
    uint32_t* As = Bs + 128 * BPITCH;
    float* sbias = (float*)(As + 2 * BM * APITCH);

    const int tid  = threadIdx.x;
    const int wid  = tid >> 5;
    const int lane = tid & 31;
    const int wm = (wid >> 1) * 32;
    const int wn = (wid & 1) * 64;

    for (int u = tid; u < 128 * 128; u += 512) {
        int j = u >> 7, k = u & 127;
        int kin = k & 7;
        int kp = (k & ~7) | (((kin & 3) << 1) | (kin >> 2));
        Bs[j * BPITCH + kp]       = tf32r(Wself[u]);
        Bs[j * BPITCH + 128 + kp] = tf32r(Wneigh[u]);
    }
    if (tid < 128) sbias[tid] = bias[tid];
    __syncthreads();

    const int ntiles = (n_nodes + BM - 1) / BM;
    const int r0s = tid >> 3, f4 = tid & 7;

    for (int tile = blockIdx.x; tile < ntiles; tile += gridDim.x) {
        const int nodeBase = tile * BM;

        float acc[2][8][4];
        #pragma unroll
        for (int mi = 0; mi < 2; mi++)
            #pragma unroll
            for (int ni = 0; ni < 8; ni++)
                #pragma unroll
                for (int q = 0; q < 4; q++) acc[mi][ni][q] = 0.f;

        float4 pv[4];
        #pragma unroll
        for (int i = 0; i < 4; i++) {
            int node = nodeBase + r0s + i * 64;
            pv[i] = (node < n_nodes)
                ? *reinterpret_cast<const float4*>(h + (size_t)node * D + f4 * 4)
                : make_float4(0.f, 0.f, 0.f, 0.f);
        }

        #pragma unroll 1
        for (int c = 0; c < 8; c++) {
            uint32_t* bufA = As + (c & 1) * (BM * APITCH);

            #pragma unroll
            for (int i = 0; i < 4; i++) {
                int r = r0s + i * 64;
                uint32_t* p = bufA + r * APITCH + f4 * 4;
                p[0] = tf32r(pv[i].x);
                p[1] = tf32r(pv[i].y);
                p[2] = tf32r(pv[i].z);
                p[3] = tf32r(pv[i].w);
            }

            if (c < 7) {
                const int cn = c + 1;
                const float* X = (cn < 4) ? h : g_neigh;
                const int koff = (cn & 3) * 32;
                #pragma unroll
                for (int i = 0; i < 4; i++) {
                    int node = nodeBase + r0s + i * 64;
                    pv[i] = (node < n_nodes)
                        ? *reinterpret_cast<const float4*>(X + (size_t)node * D + koff + f4 * 4)
                        : make_float4(0.f, 0.f, 0.f, 0.f);
                }
            }
            __syncthreads();

            #pragma unroll
            for (int kf = 0; kf < 4; kf++) {
                const int kb = kf * 8;
                uint32_t a[2][4];
                #pragma unroll
                for (int mi = 0; mi < 2; mi++) {
                    const uint32_t* pa =
                        bufA + (wm + mi * 16 + (lane >> 2)) * APITCH + kb + (lane & 3);
                    a[mi][0] = pa[0];
                    a[mi][1] = pa[8 * APITCH];
                    a[mi][2] = pa[4];
                    a[mi][3] = pa[8 * APITCH + 4];
                }
                #pragma unroll
                for (int ni = 0; ni < 8; ni++) {
                    const uint2 bb = *reinterpret_cast<const uint2*>(
                        Bs + (wn + ni * 8 + (lane >> 2)) * BPITCH + c * 32 + kb + 2 * (lane & 3));
                    #pragma unroll
                    for (int mi = 0; mi < 2; mi++)
                        mma1688(acc[mi][ni], a[mi], bb.x, bb.y);
                }
            }
            __syncthreads();
        }

        #pragma unroll
        for (int mi = 0; mi < 2; mi++) {
            int r0 = nodeBase + wm + mi * 16 + (lane >> 2);
            int r1 = r0 + 8;
            #pragma unroll
            for (int ni = 0; ni < 8; ni++) {
                int col = wn + ni * 8 + (lane & 3) * 2;
                float b0 = sbias[col], b1 = sbias[col + 1];
                if (r0 < n_nodes) {
                    float2 v = make_float2(acc[mi][ni][0] + b0, acc[mi][ni][1] + b1);
                    *reinterpret_cast<float2*>(out + (size_t)r0 * D + col) = v;
                }
                if (r1 < n_nodes) {
                    float2 v = make_float2(acc[mi][ni][2] + b0, acc[mi][ni][3] + b1);
                    *reinterpret_cast<float2*>(out + (size_t)r1 * D + col) = v;
                }
            }
        }
    }
}

// ---------------------------------------------------------------------------
extern "C" void kernel_launch(void* const* d_in, const int* in_sizes, int n_in,
                              void* d_out, int out_size)
{
    const float* h      = (const float*)d_in[0];
    const int*   src32  = (const int*)d_in[1];
    const int*   dst32  = (const int*)d_in[2];
    const float* Wself  = (const float*)d_in[3];
    const float* Wneigh = (const float*)d_in[4];
    const float* bias   = (const float*)d_in[5];
    float*       out    = (float*)d_out;

    const int n_nodes = in_sizes[0] / D;
    const int n_edges = in_sizes[1];

    static int attr_set = 0;
    if (!attr_set) {
        cudaFuncSetAttribute(sage_mma_kernel,
                             cudaFuncAttributeMaxDynamicSharedMemorySize, SMEM_BYTES);
        attr_set = 1;
    }

    const int prep_elems = NN * D / 4 + NN / 4;
    prep_kernel<<<(prep_elems + 255) / 256, 256>>>(h);

    const int n_pairs = (n_edges + 1) / 2;
    bin_kernel<<<(n_pairs + 255) / 256, 256>>>(src32, dst32, n_edges);

    agg_kernel<<<(n_nodes * 32 + 255) / 256, 256>>>(n_nodes);
    sage_mma_kernel<<<148, 512, SMEM_BYTES>>>(h, Wself, Wneigh, bias, out, n_nodes);
}